// round 5
// baseline (speedup 1.0000x reference)
#include <cuda_runtime.h>

#define NN   50000
#define EE   800000
#define DF   128
#define NCLS 3
#define MQ   10000

// Scratch (static device globals — no runtime allocation).
__device__ __align__(16) float g_H[(size_t)NN * DF];
__device__ __align__(16) float g_A[(size_t)NN * DF];
__device__ __align__(16) float g_logits[(size_t)NN * NCLS];
__device__ int g_deg[NN];
__device__ int g_off[NN];
__device__ int g_rank[EE];
__device__ int g_csr[EE];

// ---------------------------------------------------------------------------
// CSR build: zero -> histogram(dst) capturing per-edge rank -> scan -> fill
// (fill has NO atomics: position = off[dst] + rank[e])
// ---------------------------------------------------------------------------
__global__ void zero_deg_kernel()
{
    int i = blockIdx.x * blockDim.x + threadIdx.x;
    if (i < NN) g_deg[i] = 0;
}

__global__ void hist_kernel(const int* __restrict__ edges)
{
    int e = blockIdx.x * blockDim.x + threadIdx.x;
    if (e >= EE) return;
    int dst = edges[EE + e];
    int r = 0;
    if ((unsigned)dst < NN) r = atomicAdd(&g_deg[dst], 1);
    g_rank[e] = r;
}

__global__ void __launch_bounds__(1024) scan_kernel()
{
    __shared__ int sh[1024];
    const int T = 1024;
    const int CH = (NN + T - 1) / T;          // 49
    int t = threadIdx.x;
    int start = t * CH;
    int end   = min(start + CH, NN);

    int s = 0;
    for (int i = start; i < end; i++) s += g_deg[i];
    sh[t] = s;
    __syncthreads();

    for (int off = 1; off < T; off <<= 1) {
        int v = (t >= off) ? sh[t - off] : 0;
        __syncthreads();
        sh[t] += v;
        __syncthreads();
    }
    int run = sh[t] - s;   // exclusive prefix for this thread's chunk
    for (int i = start; i < end; i++) {
        g_off[i] = run;
        run += g_deg[i];
    }
}

__global__ void fill_kernel(const int* __restrict__ edges)
{
    int e = blockIdx.x * blockDim.x + threadIdx.x;
    if (e >= EE) return;
    int dst = edges[EE + e];
    int src = edges[e];
    if ((unsigned)dst >= NN || (unsigned)src >= NN) return;
    g_csr[g_off[dst] + g_rank[e]] = src;
}

// ---------------------------------------------------------------------------
// GEMM: H[r][n] = sum_k act(X[r][k]) * W[n][k] + b[n]
// BM=128, BN=128, BK=16; 256 threads; 8x8 tile; double-buffered smem
// (2*2*16*132*4 = 33.8 KB, fits static limit); stride 132 padding.
// ---------------------------------------------------------------------------
#define LDP 132

template <bool RELU_IN>
__global__ void __launch_bounds__(256) gemm_kernel(
    const float* __restrict__ X, const float* __restrict__ W,
    const float* __restrict__ bias, float* __restrict__ H)
{
    __shared__ float Xs[2][16][LDP];
    __shared__ float Ws[2][16][LDP];

    const int tid  = threadIdx.x;
    const int row0 = blockIdx.x * 128;
    const int tr   = tid >> 4;
    const int tc   = tid & 15;

    float acc[8][8] = {};

    auto load_tiles = [&](int kb, int s) {
        // 128 rows x 16 k = 512 float4 loads; 2 per thread
        #pragma unroll
        for (int i = 0; i < 2; i++) {
            int idx = tid + i * 256;          // 0..511
            int r   = idx >> 2;               // 0..127
            int c4  = idx & 3;                // 0..3
            int gr  = row0 + r;
            float4 v = make_float4(0.f, 0.f, 0.f, 0.f);
            if (gr < NN)
                v = *reinterpret_cast<const float4*>(X + (size_t)gr * DF + kb + c4 * 4);
            if (RELU_IN) {
                v.x = fmaxf(v.x, 0.f); v.y = fmaxf(v.y, 0.f);
                v.z = fmaxf(v.z, 0.f); v.w = fmaxf(v.w, 0.f);
            }
            Xs[s][c4 * 4 + 0][r] = v.x; Xs[s][c4 * 4 + 1][r] = v.y;
            Xs[s][c4 * 4 + 2][r] = v.z; Xs[s][c4 * 4 + 3][r] = v.w;
        }
        #pragma unroll
        for (int i = 0; i < 2; i++) {
            int idx = tid + i * 256;
            int n   = idx >> 2;
            int c4  = idx & 3;
            float4 v = *reinterpret_cast<const float4*>(W + (size_t)n * DF + kb + c4 * 4);
            Ws[s][c4 * 4 + 0][n] = v.x; Ws[s][c4 * 4 + 1][n] = v.y;
            Ws[s][c4 * 4 + 2][n] = v.z; Ws[s][c4 * 4 + 3][n] = v.w;
        }
    };

    load_tiles(0, 0);
    __syncthreads();

    int cur = 0;
    #pragma unroll
    for (int kb = 0; kb < 8; kb++) {
        if (kb < 7) load_tiles((kb + 1) * 16, cur ^ 1);

        #pragma unroll
        for (int k = 0; k < 16; k++) {
            float4 m0 = *reinterpret_cast<const float4*>(&Xs[cur][k][tr * 8]);
            float4 m1 = *reinterpret_cast<const float4*>(&Xs[cur][k][tr * 8 + 4]);
            float4 n0 = *reinterpret_cast<const float4*>(&Ws[cur][k][tc * 8]);
            float4 n1 = *reinterpret_cast<const float4*>(&Ws[cur][k][tc * 8 + 4]);
            float rm[8] = {m0.x, m0.y, m0.z, m0.w, m1.x, m1.y, m1.z, m1.w};
            float rn[8] = {n0.x, n0.y, n0.z, n0.w, n1.x, n1.y, n1.z, n1.w};
            #pragma unroll
            for (int i = 0; i < 8; i++)
                #pragma unroll
                for (int j = 0; j < 8; j++)
                    acc[i][j] += rm[i] * rn[j];
        }
        __syncthreads();
        cur ^= 1;
    }

    float bn[8];
    #pragma unroll
    for (int j = 0; j < 8; j++) bn[j] = bias[tc * 8 + j];

    #pragma unroll
    for (int i = 0; i < 8; i++) {
        int gr = row0 + tr * 8 + i;
        if (gr < NN) {
            #pragma unroll
            for (int j = 0; j < 8; j += 4) {
                float4 v;
                v.x = acc[i][j + 0] + bn[j + 0];
                v.y = acc[i][j + 1] + bn[j + 1];
                v.z = acc[i][j + 2] + bn[j + 2];
                v.w = acc[i][j + 3] + bn[j + 3];
                *reinterpret_cast<float4*>(H + (size_t)gr * DF + tc * 8 + j) = v;
            }
        }
    }
}

// ---------------------------------------------------------------------------
// Gather segment-sum: AGG[n] = H[n] + sum_{s in csr[n]} H[s]. One warp/node.
// ---------------------------------------------------------------------------
__device__ __forceinline__ float4 gather_row(int node, int lane,
                                             const float* __restrict__ H)
{
    int start = g_off[node];
    int deg   = g_deg[node];

    float4 acc = *reinterpret_cast<const float4*>(H + (size_t)node * DF + lane * 4);

    for (int j = 0; j < deg; j += 32) {
        int rem  = deg - j;
        int cnt  = rem < 32 ? rem : 32;
        int myi  = (lane < cnt) ? g_csr[start + j + lane] : 0;
        #pragma unroll 4
        for (int k = 0; k < cnt; k++) {
            int s = __shfl_sync(0xffffffffu, myi, k);
            float4 v = *reinterpret_cast<const float4*>(H + (size_t)s * DF + lane * 4);
            acc.x += v.x; acc.y += v.y; acc.z += v.z; acc.w += v.w;
        }
    }
    return acc;
}

__global__ void __launch_bounds__(256) gather_kernel(
    const float* __restrict__ H, float* __restrict__ AGG)
{
    const int w    = (blockIdx.x * blockDim.x + threadIdx.x) >> 5;
    const int lane = threadIdx.x & 31;
    if (w >= NN) return;
    float4 acc = gather_row(w, lane, H);
    *reinterpret_cast<float4*>(AGG + (size_t)w * DF + lane * 4) = acc;
}

// Layer-3 gather fused with head: relu, x_embed, logits, argmax.
__global__ void __launch_bounds__(256) gather_head_kernel(
    const float* __restrict__ H, const float* __restrict__ Wout,
    const float* __restrict__ bout, float* __restrict__ out)
{
    const int w    = (blockIdx.x * blockDim.x + threadIdx.x) >> 5;
    const int lane = threadIdx.x & 31;
    if (w >= NN) return;

    float4 v = gather_row(w, lane, H);
    v.x = fmaxf(v.x, 0.f); v.y = fmaxf(v.y, 0.f);
    v.z = fmaxf(v.z, 0.f); v.w = fmaxf(v.w, 0.f);
    *reinterpret_cast<float4*>(out + (size_t)w * DF + lane * 4) = v;  // x_embed

    float l0, l1, l2;
    {
        float4 w0 = *reinterpret_cast<const float4*>(Wout + 0 * DF + lane * 4);
        float4 w1 = *reinterpret_cast<const float4*>(Wout + 1 * DF + lane * 4);
        float4 w2 = *reinterpret_cast<const float4*>(Wout + 2 * DF + lane * 4);
        l0 = v.x * w0.x + v.y * w0.y + v.z * w0.z + v.w * w0.w;
        l1 = v.x * w1.x + v.y * w1.y + v.z * w1.z + v.w * w1.w;
        l2 = v.x * w2.x + v.y * w2.y + v.z * w2.z + v.w * w2.w;
    }
    #pragma unroll
    for (int off = 16; off > 0; off >>= 1) {
        l0 += __shfl_xor_sync(0xffffffffu, l0, off);
        l1 += __shfl_xor_sync(0xffffffffu, l1, off);
        l2 += __shfl_xor_sync(0xffffffffu, l2, off);
    }
    if (lane == 0) {
        l0 += bout[0]; l1 += bout[1]; l2 += bout[2];
        g_logits[(size_t)w * 3 + 0] = l0;
        g_logits[(size_t)w * 3 + 1] = l1;
        g_logits[(size_t)w * 3 + 2] = l2;
        int am = 0; float best = l0;
        if (l1 > best) { best = l1; am = 1; }
        if (l2 > best) { best = l2; am = 2; }
        out[(size_t)NN * DF + (size_t)MQ * NCLS + w] = (float)am;  // ypred
    }
}

// node_output = logits[node_index]; y_nodepred = ypred[node_index]
__global__ void node_gather_kernel(const int* __restrict__ node_index,
                                   float* __restrict__ out)
{
    int i = blockIdx.x * blockDim.x + threadIdx.x;
    if (i >= MQ) return;
    int n = node_index[i];
    if ((unsigned)n >= NN) n = 0;
    size_t base = (size_t)NN * DF;
    out[base + (size_t)i * 3 + 0] = g_logits[(size_t)n * 3 + 0];
    out[base + (size_t)i * 3 + 1] = g_logits[(size_t)n * 3 + 1];
    out[base + (size_t)i * 3 + 2] = g_logits[(size_t)n * 3 + 2];
    out[base + (size_t)MQ * NCLS + NN + i] = out[base + (size_t)MQ * NCLS + n];
}

// ---------------------------------------------------------------------------
extern "C" void kernel_launch(void* const* d_in, const int* in_sizes, int n_in,
                              void* d_out, int out_size)
{
    const float* x          = (const float*)d_in[0];
    const int*   edges      = (const int*)d_in[1];
    /* d_in[2] node_label: unused (zeros) */
    const int*   node_index = (const int*)d_in[3];
    const float* W1 = (const float*)d_in[4];  const float* b1 = (const float*)d_in[5];
    const float* W2 = (const float*)d_in[6];  const float* b2 = (const float*)d_in[7];
    const float* W3 = (const float*)d_in[8];  const float* b3 = (const float*)d_in[9];
    const float* Wout = (const float*)d_in[10]; const float* bout = (const float*)d_in[11];
    float* out = (float*)d_out;

    float *H, *A;
    cudaGetSymbolAddress((void**)&H, g_H);
    cudaGetSymbolAddress((void**)&A, g_A);

    const int gemm_blocks = (NN + 127) / 128;               // 391
    const int edge_blocks = (EE + 255) / 256;               // 3125
    const int warp_blocks = ((size_t)NN * 32 + 255) / 256;  // 6250

    // CSR build (no atomics in fill)
    zero_deg_kernel<<<(NN + 255) / 256, 256>>>();
    hist_kernel<<<edge_blocks, 256>>>(edges);
    scan_kernel<<<1, 1024>>>();
    fill_kernel<<<edge_blocks, 256>>>(edges);

    // Layer 1
    gemm_kernel<false><<<gemm_blocks, 256>>>(x, W1, b1, H);
    gather_kernel<<<warp_blocks, 256>>>(H, A);
    // Layer 2 (relu on read)
    gemm_kernel<true><<<gemm_blocks, 256>>>(A, W2, b2, H);
    gather_kernel<<<warp_blocks, 256>>>(H, A);
    // Layer 3 + fused head
    gemm_kernel<true><<<gemm_blocks, 256>>>(A, W3, b3, H);
    gather_head_kernel<<<warp_blocks, 256>>>(H, Wout, bout, out);

    node_gather_kernel<<<(MQ + 255) / 256, 256>>>(node_index, out);
}

// round 6
// speedup vs baseline: 1.2715x; 1.2715x over previous
#include <cuda_runtime.h>

#define NN   50000
#define EE   800000
#define DF   128
#define NCLS 3
#define MQ   10000

// Scratch (static device globals — no runtime allocation).
__device__ __align__(16) float g_H[(size_t)NN * DF];
__device__ __align__(16) float g_A[(size_t)NN * DF];
__device__ __align__(16) float g_logits[(size_t)NN * NCLS];
__device__ int g_deg[NN];
__device__ int g_off[NN];
__device__ int g_rank[EE];
__device__ int g_csr[EE];

// ---------------------------------------------------------------------------
// Packed f32x2 helpers (Blackwell sm_100a+)
// ---------------------------------------------------------------------------
__device__ __forceinline__ unsigned long long pack2(float lo, float hi)
{
    unsigned long long r;
    asm("mov.b64 %0, {%1, %2};" : "=l"(r) : "f"(lo), "f"(hi));
    return r;
}
__device__ __forceinline__ unsigned long long splat2(float v)
{
    unsigned long long r;
    asm("mov.b64 %0, {%1, %1};" : "=l"(r) : "f"(v));
    return r;
}
__device__ __forceinline__ void fma2(unsigned long long& d,
                                     unsigned long long a, unsigned long long b)
{
    asm("fma.rn.f32x2 %0, %1, %2, %0;" : "+l"(d) : "l"(a), "l"(b));
}
__device__ __forceinline__ void unpack2(unsigned long long v, float& lo, float& hi)
{
    asm("mov.b64 {%0, %1}, %2;" : "=f"(lo), "=f"(hi) : "l"(v));
}

// ---------------------------------------------------------------------------
// CSR build: zero -> histogram(dst) capturing per-edge rank -> scan -> fill
// (fill has NO atomics: position = off[dst] + rank[e])
// ---------------------------------------------------------------------------
__global__ void zero_deg_kernel()
{
    int i = blockIdx.x * blockDim.x + threadIdx.x;
    if (i < NN) g_deg[i] = 0;
}

__global__ void hist_kernel(const int* __restrict__ edges)
{
    int e = blockIdx.x * blockDim.x + threadIdx.x;
    if (e >= EE) return;
    int dst = edges[EE + e];
    int r = 0;
    if ((unsigned)dst < NN) r = atomicAdd(&g_deg[dst], 1);
    g_rank[e] = r;
}

__global__ void __launch_bounds__(1024) scan_kernel()
{
    __shared__ int sh[1024];
    const int T = 1024;
    const int CH = (NN + T - 1) / T;          // 49
    int t = threadIdx.x;
    int start = t * CH;
    int end   = min(start + CH, NN);

    int s = 0;
    for (int i = start; i < end; i++) s += g_deg[i];
    sh[t] = s;
    __syncthreads();

    for (int off = 1; off < T; off <<= 1) {
        int v = (t >= off) ? sh[t - off] : 0;
        __syncthreads();
        sh[t] += v;
        __syncthreads();
    }
    int run = sh[t] - s;   // exclusive prefix for this thread's chunk
    for (int i = start; i < end; i++) {
        g_off[i] = run;
        run += g_deg[i];
    }
}

__global__ void fill_kernel(const int* __restrict__ edges)
{
    int e = blockIdx.x * blockDim.x + threadIdx.x;
    if (e >= EE) return;
    int dst = edges[EE + e];
    int src = edges[e];
    if ((unsigned)dst >= NN || (unsigned)src >= NN) return;
    g_csr[g_off[dst] + g_rank[e]] = src;
}

// ---------------------------------------------------------------------------
// GEMM: H[r][n] = sum_k act(X[r][k]) * W[n][k] + b[n]
// BM=128, BN=128, BK=32; 256 threads; 8x8 tile computed as 4 row-pairs x 8
// cols of packed f32x2 FMAs. Single-buffer smem, stride 132 padding
// (2*32*132*4 = 33.8 KB static).
// ---------------------------------------------------------------------------
#define LDP 132

template <bool RELU_IN>
__global__ void __launch_bounds__(256) gemm_kernel(
    const float* __restrict__ X, const float* __restrict__ W,
    const float* __restrict__ bias, float* __restrict__ H)
{
    __shared__ float Xs[32][LDP];   // Xs[k][m]
    __shared__ float Ws[32][LDP];   // Ws[k][n] = W[n][k_global]

    const int tid  = threadIdx.x;
    const int row0 = blockIdx.x * 128;
    const int tr   = tid >> 4;
    const int tc   = tid & 15;

    unsigned long long acc2[4][8];  // [row-pair][col] : (acc[2i][j], acc[2i+1][j])
    #pragma unroll
    for (int i = 0; i < 4; i++)
        #pragma unroll
        for (int j = 0; j < 8; j++) acc2[i][j] = 0ull;

    for (int kb = 0; kb < DF; kb += 32) {
        #pragma unroll
        for (int i = 0; i < 4; i++) {
            int idx = tid + i * 256;          // 0..1023
            int r   = idx >> 3;               // 0..127
            int c4  = idx & 7;                // 0..7
            int gr  = row0 + r;
            float4 v = make_float4(0.f, 0.f, 0.f, 0.f);
            if (gr < NN)
                v = *reinterpret_cast<const float4*>(X + (size_t)gr * DF + kb + c4 * 4);
            if (RELU_IN) {
                v.x = fmaxf(v.x, 0.f); v.y = fmaxf(v.y, 0.f);
                v.z = fmaxf(v.z, 0.f); v.w = fmaxf(v.w, 0.f);
            }
            Xs[c4 * 4 + 0][r] = v.x; Xs[c4 * 4 + 1][r] = v.y;
            Xs[c4 * 4 + 2][r] = v.z; Xs[c4 * 4 + 3][r] = v.w;
        }
        #pragma unroll
        for (int i = 0; i < 4; i++) {
            int idx = tid + i * 256;
            int n   = idx >> 3;
            int c4  = idx & 7;
            float4 v = *reinterpret_cast<const float4*>(W + (size_t)n * DF + kb + c4 * 4);
            Ws[c4 * 4 + 0][n] = v.x; Ws[c4 * 4 + 1][n] = v.y;
            Ws[c4 * 4 + 2][n] = v.z; Ws[c4 * 4 + 3][n] = v.w;
        }
        __syncthreads();

        #pragma unroll
        for (int k = 0; k < 32; k++) {
            float4 m0 = *reinterpret_cast<const float4*>(&Xs[k][tr * 8]);
            float4 m1 = *reinterpret_cast<const float4*>(&Xs[k][tr * 8 + 4]);
            float4 n0 = *reinterpret_cast<const float4*>(&Ws[k][tc * 8]);
            float4 n1 = *reinterpret_cast<const float4*>(&Ws[k][tc * 8 + 4]);

            unsigned long long ap[4];
            ap[0] = pack2(m0.x, m0.y); ap[1] = pack2(m0.z, m0.w);
            ap[2] = pack2(m1.x, m1.y); ap[3] = pack2(m1.z, m1.w);

            unsigned long long bs[8];
            bs[0] = splat2(n0.x); bs[1] = splat2(n0.y);
            bs[2] = splat2(n0.z); bs[3] = splat2(n0.w);
            bs[4] = splat2(n1.x); bs[5] = splat2(n1.y);
            bs[6] = splat2(n1.z); bs[7] = splat2(n1.w);

            #pragma unroll
            for (int i = 0; i < 4; i++)
                #pragma unroll
                for (int j = 0; j < 8; j++)
                    fma2(acc2[i][j], ap[i], bs[j]);
        }
        __syncthreads();
    }

    float bn[8];
    #pragma unroll
    for (int j = 0; j < 8; j++) bn[j] = bias[tc * 8 + j];

    // Unpack: acc2[i2][j] = (acc[2*i2][j], acc[2*i2+1][j])
    float accf[8][8];
    #pragma unroll
    for (int i2 = 0; i2 < 4; i2++)
        #pragma unroll
        for (int j = 0; j < 8; j++)
            unpack2(acc2[i2][j], accf[2 * i2][j], accf[2 * i2 + 1][j]);

    #pragma unroll
    for (int i = 0; i < 8; i++) {
        int gr = row0 + tr * 8 + i;
        if (gr < NN) {
            #pragma unroll
            for (int j = 0; j < 8; j += 4) {
                float4 v;
                v.x = accf[i][j + 0] + bn[j + 0];
                v.y = accf[i][j + 1] + bn[j + 1];
                v.z = accf[i][j + 2] + bn[j + 2];
                v.w = accf[i][j + 3] + bn[j + 3];
                *reinterpret_cast<float4*>(H + (size_t)gr * DF + tc * 8 + j) = v;
            }
        }
    }
}

// ---------------------------------------------------------------------------
// Gather segment-sum: AGG[n] = H[n] + sum_{s in csr[n]} H[s]. One warp/node.
// ---------------------------------------------------------------------------
__device__ __forceinline__ float4 gather_row(int node, int lane,
                                             const float* __restrict__ H)
{
    int start = g_off[node];
    int deg   = g_deg[node];

    float4 acc = *reinterpret_cast<const float4*>(H + (size_t)node * DF + lane * 4);

    for (int j = 0; j < deg; j += 32) {
        int rem  = deg - j;
        int cnt  = rem < 32 ? rem : 32;
        int myi  = (lane < cnt) ? g_csr[start + j + lane] : 0;
        #pragma unroll 4
        for (int k = 0; k < cnt; k++) {
            int s = __shfl_sync(0xffffffffu, myi, k);
            float4 v = *reinterpret_cast<const float4*>(H + (size_t)s * DF + lane * 4);
            acc.x += v.x; acc.y += v.y; acc.z += v.z; acc.w += v.w;
        }
    }
    return acc;
}

__global__ void __launch_bounds__(256) gather_kernel(
    const float* __restrict__ H, float* __restrict__ AGG)
{
    const int w    = (blockIdx.x * blockDim.x + threadIdx.x) >> 5;
    const int lane = threadIdx.x & 31;
    if (w >= NN) return;
    float4 acc = gather_row(w, lane, H);
    *reinterpret_cast<float4*>(AGG + (size_t)w * DF + lane * 4) = acc;
}

// Layer-3 gather fused with head: relu, x_embed, logits, argmax.
__global__ void __launch_bounds__(256) gather_head_kernel(
    const float* __restrict__ H, const float* __restrict__ Wout,
    const float* __restrict__ bout, float* __restrict__ out)
{
    const int w    = (blockIdx.x * blockDim.x + threadIdx.x) >> 5;
    const int lane = threadIdx.x & 31;
    if (w >= NN) return;

    float4 v = gather_row(w, lane, H);
    v.x = fmaxf(v.x, 0.f); v.y = fmaxf(v.y, 0.f);
    v.z = fmaxf(v.z, 0.f); v.w = fmaxf(v.w, 0.f);
    *reinterpret_cast<float4*>(out + (size_t)w * DF + lane * 4) = v;  // x_embed

    float l0, l1, l2;
    {
        float4 w0 = *reinterpret_cast<const float4*>(Wout + 0 * DF + lane * 4);
        float4 w1 = *reinterpret_cast<const float4*>(Wout + 1 * DF + lane * 4);
        float4 w2 = *reinterpret_cast<const float4*>(Wout + 2 * DF + lane * 4);
        l0 = v.x * w0.x + v.y * w0.y + v.z * w0.z + v.w * w0.w;
        l1 = v.x * w1.x + v.y * w1.y + v.z * w1.z + v.w * w1.w;
        l2 = v.x * w2.x + v.y * w2.y + v.z * w2.z + v.w * w2.w;
    }
    #pragma unroll
    for (int off = 16; off > 0; off >>= 1) {
        l0 += __shfl_xor_sync(0xffffffffu, l0, off);
        l1 += __shfl_xor_sync(0xffffffffu, l1, off);
        l2 += __shfl_xor_sync(0xffffffffu, l2, off);
    }
    if (lane == 0) {
        l0 += bout[0]; l1 += bout[1]; l2 += bout[2];
        g_logits[(size_t)w * 3 + 0] = l0;
        g_logits[(size_t)w * 3 + 1] = l1;
        g_logits[(size_t)w * 3 + 2] = l2;
        int am = 0; float best = l0;
        if (l1 > best) { best = l1; am = 1; }
        if (l2 > best) { best = l2; am = 2; }
        out[(size_t)NN * DF + (size_t)MQ * NCLS + w] = (float)am;  // ypred
    }
}

// node_output = logits[node_index]; y_nodepred = ypred[node_index]
__global__ void node_gather_kernel(const int* __restrict__ node_index,
                                   float* __restrict__ out)
{
    int i = blockIdx.x * blockDim.x + threadIdx.x;
    if (i >= MQ) return;
    int n = node_index[i];
    if ((unsigned)n >= NN) n = 0;
    size_t base = (size_t)NN * DF;
    out[base + (size_t)i * 3 + 0] = g_logits[(size_t)n * 3 + 0];
    out[base + (size_t)i * 3 + 1] = g_logits[(size_t)n * 3 + 1];
    out[base + (size_t)i * 3 + 2] = g_logits[(size_t)n * 3 + 2];
    out[base + (size_t)MQ * NCLS + NN + i] = out[base + (size_t)MQ * NCLS + n];
}

// ---------------------------------------------------------------------------
extern "C" void kernel_launch(void* const* d_in, const int* in_sizes, int n_in,
                              void* d_out, int out_size)
{
    const float* x          = (const float*)d_in[0];
    const int*   edges      = (const int*)d_in[1];
    /* d_in[2] node_label: unused (zeros) */
    const int*   node_index = (const int*)d_in[3];
    const float* W1 = (const float*)d_in[4];  const float* b1 = (const float*)d_in[5];
    const float* W2 = (const float*)d_in[6];  const float* b2 = (const float*)d_in[7];
    const float* W3 = (const float*)d_in[8];  const float* b3 = (const float*)d_in[9];
    const float* Wout = (const float*)d_in[10]; const float* bout = (const float*)d_in[11];
    float* out = (float*)d_out;

    float *H, *A;
    cudaGetSymbolAddress((void**)&H, g_H);
    cudaGetSymbolAddress((void**)&A, g_A);

    const int gemm_blocks = (NN + 127) / 128;               // 391
    const int edge_blocks = (EE + 255) / 256;               // 3125
    const int warp_blocks = ((size_t)NN * 32 + 255) / 256;  // 6250

    // CSR build (no atomics in fill)
    zero_deg_kernel<<<(NN + 255) / 256, 256>>>();
    hist_kernel<<<edge_blocks, 256>>>(edges);
    scan_kernel<<<1, 1024>>>();
    fill_kernel<<<edge_blocks, 256>>>(edges);

    // Layer 1
    gemm_kernel<false><<<gemm_blocks, 256>>>(x, W1, b1, H);
    gather_kernel<<<warp_blocks, 256>>>(H, A);
    // Layer 2 (relu on read)
    gemm_kernel<true><<<gemm_blocks, 256>>>(A, W2, b2, H);
    gather_kernel<<<warp_blocks, 256>>>(H, A);
    // Layer 3 + fused head
    gemm_kernel<true><<<gemm_blocks, 256>>>(A, W3, b3, H);
    gather_head_kernel<<<warp_blocks, 256>>>(H, Wout, bout, out);

    node_gather_kernel<<<(MQ + 255) / 256, 256>>>(node_index, out);
}

// round 7
// speedup vs baseline: 1.3330x; 1.0483x over previous
#include <cuda_runtime.h>

#define NN   50000
#define EE   800000
#define DF   128
#define NCLS 3
#define MQ   10000

// Scratch (static device globals — no runtime allocation).
__device__ __align__(16) float g_H[(size_t)NN * DF];
__device__ __align__(16) float g_A[(size_t)NN * DF];
__device__ __align__(16) float g_logits[(size_t)NN * NCLS];
__device__ int g_deg[NN];
__device__ int g_off[NN];
__device__ int g_rank[EE];
__device__ int g_csr[EE];

// Side stream + fork/join events, created at static-init (before the harness's
// memory checkpoints bracket the run; creation never happens inside capture).
struct SideStream {
    cudaStream_t s;
    cudaEvent_t  fork, join;
    SideStream() {
        cudaStreamCreateWithFlags(&s, cudaStreamNonBlocking);
        cudaEventCreateWithFlags(&fork, cudaEventDisableTiming);
        cudaEventCreateWithFlags(&join, cudaEventDisableTiming);
    }
};
static SideStream g_side;

// ---------------------------------------------------------------------------
// Packed f32x2 helpers (Blackwell sm_100a+)
// ---------------------------------------------------------------------------
__device__ __forceinline__ unsigned long long pack2(float lo, float hi)
{
    unsigned long long r;
    asm("mov.b64 %0, {%1, %2};" : "=l"(r) : "f"(lo), "f"(hi));
    return r;
}
__device__ __forceinline__ unsigned long long splat2(float v)
{
    unsigned long long r;
    asm("mov.b64 %0, {%1, %1};" : "=l"(r) : "f"(v));
    return r;
}
__device__ __forceinline__ void fma2(unsigned long long& d,
                                     unsigned long long a, unsigned long long b)
{
    asm("fma.rn.f32x2 %0, %1, %2, %0;" : "+l"(d) : "l"(a), "l"(b));
}
__device__ __forceinline__ void unpack2(unsigned long long v, float& lo, float& hi)
{
    asm("mov.b64 {%0, %1}, %2;" : "=f"(lo), "=f"(hi) : "l"(v));
}

// ---------------------------------------------------------------------------
// CSR build: memset(deg) -> histogram(dst) capturing per-edge rank -> scan ->
// fill (NO atomics in fill: position = off[dst] + rank[e])
// ---------------------------------------------------------------------------
__global__ void hist_kernel(const int* __restrict__ edges)
{
    int e = blockIdx.x * blockDim.x + threadIdx.x;
    if (e >= EE) return;
    int dst = edges[EE + e];
    int r = 0;
    if ((unsigned)dst < NN) r = atomicAdd(&g_deg[dst], 1);
    g_rank[e] = r;
}

__global__ void __launch_bounds__(1024) scan_kernel()
{
    __shared__ int sh[1024];
    const int T = 1024;
    const int CH = (NN + T - 1) / T;          // 49
    int t = threadIdx.x;
    int start = t * CH;
    int end   = min(start + CH, NN);

    int s = 0;
    for (int i = start; i < end; i++) s += g_deg[i];
    sh[t] = s;
    __syncthreads();

    for (int off = 1; off < T; off <<= 1) {
        int v = (t >= off) ? sh[t - off] : 0;
        __syncthreads();
        sh[t] += v;
        __syncthreads();
    }
    int run = sh[t] - s;   // exclusive prefix for this thread's chunk
    for (int i = start; i < end; i++) {
        g_off[i] = run;
        run += g_deg[i];
    }
}

__global__ void fill_kernel(const int* __restrict__ edges)
{
    int e = blockIdx.x * blockDim.x + threadIdx.x;
    if (e >= EE) return;
    int dst = edges[EE + e];
    int src = edges[e];
    if ((unsigned)dst >= NN || (unsigned)src >= NN) return;
    g_csr[g_off[dst] + g_rank[e]] = src;
}

// ---------------------------------------------------------------------------
// GEMM: H[r][n] = sum_k act(X[r][k]) * W[n][k] + b[n]
// BM=128, BN=128, BK=32; 256 threads; 8x8 tile as 4 row-pairs x 8 cols of
// packed f32x2 FMAs. Single-buffer smem, stride-132 padding (33.8 KB static).
// ---------------------------------------------------------------------------
#define LDP 132

template <bool RELU_IN>
__global__ void __launch_bounds__(256) gemm_kernel(
    const float* __restrict__ X, const float* __restrict__ W,
    const float* __restrict__ bias, float* __restrict__ H)
{
    __shared__ float Xs[32][LDP];   // Xs[k][m]
    __shared__ float Ws[32][LDP];   // Ws[k][n] = W[n][k_global]

    const int tid  = threadIdx.x;
    const int row0 = blockIdx.x * 128;
    const int tr   = tid >> 4;
    const int tc   = tid & 15;

    unsigned long long acc2[4][8];  // [row-pair][col]
    #pragma unroll
    for (int i = 0; i < 4; i++)
        #pragma unroll
        for (int j = 0; j < 8; j++) acc2[i][j] = 0ull;

    for (int kb = 0; kb < DF; kb += 32) {
        #pragma unroll
        for (int i = 0; i < 4; i++) {
            int idx = tid + i * 256;          // 0..1023
            int r   = idx >> 3;               // 0..127
            int c4  = idx & 7;                // 0..7
            int gr  = row0 + r;
            float4 v = make_float4(0.f, 0.f, 0.f, 0.f);
            if (gr < NN)
                v = *reinterpret_cast<const float4*>(X + (size_t)gr * DF + kb + c4 * 4);
            if (RELU_IN) {
                v.x = fmaxf(v.x, 0.f); v.y = fmaxf(v.y, 0.f);
                v.z = fmaxf(v.z, 0.f); v.w = fmaxf(v.w, 0.f);
            }
            Xs[c4 * 4 + 0][r] = v.x; Xs[c4 * 4 + 1][r] = v.y;
            Xs[c4 * 4 + 2][r] = v.z; Xs[c4 * 4 + 3][r] = v.w;
        }
        #pragma unroll
        for (int i = 0; i < 4; i++) {
            int idx = tid + i * 256;
            int n   = idx >> 3;
            int c4  = idx & 7;
            float4 v = *reinterpret_cast<const float4*>(W + (size_t)n * DF + kb + c4 * 4);
            Ws[c4 * 4 + 0][n] = v.x; Ws[c4 * 4 + 1][n] = v.y;
            Ws[c4 * 4 + 2][n] = v.z; Ws[c4 * 4 + 3][n] = v.w;
        }
        __syncthreads();

        #pragma unroll
        for (int k = 0; k < 32; k++) {
            float4 m0 = *reinterpret_cast<const float4*>(&Xs[k][tr * 8]);
            float4 m1 = *reinterpret_cast<const float4*>(&Xs[k][tr * 8 + 4]);
            float4 n0 = *reinterpret_cast<const float4*>(&Ws[k][tc * 8]);
            float4 n1 = *reinterpret_cast<const float4*>(&Ws[k][tc * 8 + 4]);

            unsigned long long ap[4];
            ap[0] = pack2(m0.x, m0.y); ap[1] = pack2(m0.z, m0.w);
            ap[2] = pack2(m1.x, m1.y); ap[3] = pack2(m1.z, m1.w);

            unsigned long long bs[8];
            bs[0] = splat2(n0.x); bs[1] = splat2(n0.y);
            bs[2] = splat2(n0.z); bs[3] = splat2(n0.w);
            bs[4] = splat2(n1.x); bs[5] = splat2(n1.y);
            bs[6] = splat2(n1.z); bs[7] = splat2(n1.w);

            #pragma unroll
            for (int i = 0; i < 4; i++)
                #pragma unroll
                for (int j = 0; j < 8; j++)
                    fma2(acc2[i][j], ap[i], bs[j]);
        }
        __syncthreads();
    }

    float bn[8];
    #pragma unroll
    for (int j = 0; j < 8; j++) bn[j] = bias[tc * 8 + j];

    float accf[8][8];
    #pragma unroll
    for (int i2 = 0; i2 < 4; i2++)
        #pragma unroll
        for (int j = 0; j < 8; j++)
            unpack2(acc2[i2][j], accf[2 * i2][j], accf[2 * i2 + 1][j]);

    #pragma unroll
    for (int i = 0; i < 8; i++) {
        int gr = row0 + tr * 8 + i;
        if (gr < NN) {
            #pragma unroll
            for (int j = 0; j < 8; j += 4) {
                float4 v;
                v.x = accf[i][j + 0] + bn[j + 0];
                v.y = accf[i][j + 1] + bn[j + 1];
                v.z = accf[i][j + 2] + bn[j + 2];
                v.w = accf[i][j + 3] + bn[j + 3];
                *reinterpret_cast<float4*>(H + (size_t)gr * DF + tc * 8 + j) = v;
            }
        }
    }
}

// ---------------------------------------------------------------------------
// Gather segment-sum: AGG[n] = H[n] + sum_{s in csr[n]} H[s]. One warp/node.
// ---------------------------------------------------------------------------
__device__ __forceinline__ float4 gather_row(int node, int lane,
                                             const float* __restrict__ H)
{
    int start = g_off[node];
    int deg   = g_deg[node];

    float4 acc = *reinterpret_cast<const float4*>(H + (size_t)node * DF + lane * 4);

    for (int j = 0; j < deg; j += 32) {
        int rem  = deg - j;
        int cnt  = rem < 32 ? rem : 32;
        int myi  = (lane < cnt) ? g_csr[start + j + lane] : 0;
        #pragma unroll 4
        for (int k = 0; k < cnt; k++) {
            int s = __shfl_sync(0xffffffffu, myi, k);
            float4 v = *reinterpret_cast<const float4*>(H + (size_t)s * DF + lane * 4);
            acc.x += v.x; acc.y += v.y; acc.z += v.z; acc.w += v.w;
        }
    }
    return acc;
}

__global__ void __launch_bounds__(256) gather_kernel(
    const float* __restrict__ H, float* __restrict__ AGG)
{
    const int w    = (blockIdx.x * blockDim.x + threadIdx.x) >> 5;
    const int lane = threadIdx.x & 31;
    if (w >= NN) return;
    float4 acc = gather_row(w, lane, H);
    *reinterpret_cast<float4*>(AGG + (size_t)w * DF + lane * 4) = acc;
}

// Layer-3 gather fused with head: relu, x_embed, logits, argmax.
__global__ void __launch_bounds__(256) gather_head_kernel(
    const float* __restrict__ H, const float* __restrict__ Wout,
    const float* __restrict__ bout, float* __restrict__ out)
{
    const int w    = (blockIdx.x * blockDim.x + threadIdx.x) >> 5;
    const int lane = threadIdx.x & 31;
    if (w >= NN) return;

    float4 v = gather_row(w, lane, H);
    v.x = fmaxf(v.x, 0.f); v.y = fmaxf(v.y, 0.f);
    v.z = fmaxf(v.z, 0.f); v.w = fmaxf(v.w, 0.f);
    *reinterpret_cast<float4*>(out + (size_t)w * DF + lane * 4) = v;  // x_embed

    float l0, l1, l2;
    {
        float4 w0 = *reinterpret_cast<const float4*>(Wout + 0 * DF + lane * 4);
        float4 w1 = *reinterpret_cast<const float4*>(Wout + 1 * DF + lane * 4);
        float4 w2 = *reinterpret_cast<const float4*>(Wout + 2 * DF + lane * 4);
        l0 = v.x * w0.x + v.y * w0.y + v.z * w0.z + v.w * w0.w;
        l1 = v.x * w1.x + v.y * w1.y + v.z * w1.z + v.w * w1.w;
        l2 = v.x * w2.x + v.y * w2.y + v.z * w2.z + v.w * w2.w;
    }
    #pragma unroll
    for (int off = 16; off > 0; off >>= 1) {
        l0 += __shfl_xor_sync(0xffffffffu, l0, off);
        l1 += __shfl_xor_sync(0xffffffffu, l1, off);
        l2 += __shfl_xor_sync(0xffffffffu, l2, off);
    }
    if (lane == 0) {
        l0 += bout[0]; l1 += bout[1]; l2 += bout[2];
        g_logits[(size_t)w * 3 + 0] = l0;
        g_logits[(size_t)w * 3 + 1] = l1;
        g_logits[(size_t)w * 3 + 2] = l2;
        int am = 0; float best = l0;
        if (l1 > best) { best = l1; am = 1; }
        if (l2 > best) { best = l2; am = 2; }
        out[(size_t)NN * DF + (size_t)MQ * NCLS + w] = (float)am;  // ypred
    }
}

// node_output = logits[node_index]; y_nodepred = ypred[node_index]
__global__ void node_gather_kernel(const int* __restrict__ node_index,
                                   float* __restrict__ out)
{
    int i = blockIdx.x * blockDim.x + threadIdx.x;
    if (i >= MQ) return;
    int n = node_index[i];
    if ((unsigned)n >= NN) n = 0;
    size_t base = (size_t)NN * DF;
    out[base + (size_t)i * 3 + 0] = g_logits[(size_t)n * 3 + 0];
    out[base + (size_t)i * 3 + 1] = g_logits[(size_t)n * 3 + 1];
    out[base + (size_t)i * 3 + 2] = g_logits[(size_t)n * 3 + 2];
    out[base + (size_t)MQ * NCLS + NN + i] = out[base + (size_t)MQ * NCLS + n];
}

// ---------------------------------------------------------------------------
extern "C" void kernel_launch(void* const* d_in, const int* in_sizes, int n_in,
                              void* d_out, int out_size)
{
    const float* x          = (const float*)d_in[0];
    const int*   edges      = (const int*)d_in[1];
    /* d_in[2] node_label: unused (zeros) */
    const int*   node_index = (const int*)d_in[3];
    const float* W1 = (const float*)d_in[4];  const float* b1 = (const float*)d_in[5];
    const float* W2 = (const float*)d_in[6];  const float* b2 = (const float*)d_in[7];
    const float* W3 = (const float*)d_in[8];  const float* b3 = (const float*)d_in[9];
    const float* Wout = (const float*)d_in[10]; const float* bout = (const float*)d_in[11];
    float* out = (float*)d_out;

    float *H, *A;
    cudaGetSymbolAddress((void**)&H, g_H);
    cudaGetSymbolAddress((void**)&A, g_A);
    int* degp;
    cudaGetSymbolAddress((void**)&degp, g_deg);

    const int gemm_blocks = (NN + 127) / 128;               // 391
    const int edge_blocks = (EE + 255) / 256;               // 3125
    const int warp_blocks = ((size_t)NN * 32 + 255) / 256;  // 6250

    // Fork: CSR build on side stream, GEMM-1 on main stream (independent).
    cudaEventRecord(g_side.fork, 0);
    cudaStreamWaitEvent(g_side.s, g_side.fork, 0);

    cudaMemsetAsync(degp, 0, NN * sizeof(int), g_side.s);
    hist_kernel<<<edge_blocks, 256, 0, g_side.s>>>(edges);
    scan_kernel<<<1, 1024, 0, g_side.s>>>();
    fill_kernel<<<edge_blocks, 256, 0, g_side.s>>>(edges);
    cudaEventRecord(g_side.join, g_side.s);

    gemm_kernel<false><<<gemm_blocks, 256>>>(x, W1, b1, H);   // main stream

    // Join: gather-1 needs both GEMM-1 and the CSR.
    cudaStreamWaitEvent(0, g_side.join, 0);

    gather_kernel<<<warp_blocks, 256>>>(H, A);
    // Layer 2 (relu on read)
    gemm_kernel<true><<<gemm_blocks, 256>>>(A, W2, b2, H);
    gather_kernel<<<warp_blocks, 256>>>(H, A);
    // Layer 3 + fused head
    gemm_kernel<true><<<gemm_blocks, 256>>>(A, W3, b3, H);
    gather_head_kernel<<<warp_blocks, 256>>>(H, Wout, bout, out);

    node_gather_kernel<<<(MQ + 255) / 256, 256>>>(node_index, out);
}

// round 8
// speedup vs baseline: 1.3551x; 1.0166x over previous
#include <cuda_runtime.h>

#define NN   50000
#define EE   800000
#define DF   128
#define NCLS 3
#define MQ   10000

// Scratch (static device globals — no runtime allocation).
__device__ __align__(16) float g_H[(size_t)NN * DF];
__device__ __align__(16) float g_A[(size_t)NN * DF];
__device__ __align__(16) float g_logits[(size_t)NN * NCLS];
__device__ int g_deg[NN];
__device__ int g_off[NN];
__device__ int g_rank[EE];
__device__ int g_csr[EE];

// Side stream + fork/join events, created at static-init.
struct SideStream {
    cudaStream_t s;
    cudaEvent_t  fork, join;
    SideStream() {
        cudaStreamCreateWithFlags(&s, cudaStreamNonBlocking);
        cudaEventCreateWithFlags(&fork, cudaEventDisableTiming);
        cudaEventCreateWithFlags(&join, cudaEventDisableTiming);
    }
};
static SideStream g_side;

// ---------------------------------------------------------------------------
// Packed f32x2 helpers (Blackwell sm_100a+)
// ---------------------------------------------------------------------------
__device__ __forceinline__ unsigned long long pack2(float lo, float hi)
{
    unsigned long long r;
    asm("mov.b64 %0, {%1, %2};" : "=l"(r) : "f"(lo), "f"(hi));
    return r;
}
__device__ __forceinline__ unsigned long long splat2(float v)
{
    unsigned long long r;
    asm("mov.b64 %0, {%1, %1};" : "=l"(r) : "f"(v));
    return r;
}
__device__ __forceinline__ void fma2(unsigned long long& d,
                                     unsigned long long a, unsigned long long b)
{
    asm("fma.rn.f32x2 %0, %1, %2, %0;" : "+l"(d) : "l"(a), "l"(b));
}
__device__ __forceinline__ void unpack2(unsigned long long v, float& lo, float& hi)
{
    asm("mov.b64 {%0, %1}, %2;" : "=f"(lo), "=f"(hi) : "l"(v));
}

// ---------------------------------------------------------------------------
// CSR build: memset(deg) -> histogram(dst) capturing per-edge rank -> scan ->
// fill (NO atomics in fill: position = off[dst] + rank[e])
// ---------------------------------------------------------------------------
__global__ void hist_kernel(const int* __restrict__ edges)
{
    int e = blockIdx.x * blockDim.x + threadIdx.x;
    if (e >= EE) return;
    int dst = edges[EE + e];
    int r = 0;
    if ((unsigned)dst < NN) r = atomicAdd(&g_deg[dst], 1);
    g_rank[e] = r;
}

__global__ void __launch_bounds__(1024) scan_kernel()
{
    __shared__ int sh[1024];
    const int T = 1024;
    const int CH = (NN + T - 1) / T;          // 49
    int t = threadIdx.x;
    int start = t * CH;
    int end   = min(start + CH, NN);

    int s = 0;
    for (int i = start; i < end; i++) s += g_deg[i];
    sh[t] = s;
    __syncthreads();

    for (int off = 1; off < T; off <<= 1) {
        int v = (t >= off) ? sh[t - off] : 0;
        __syncthreads();
        sh[t] += v;
        __syncthreads();
    }
    int run = sh[t] - s;   // exclusive prefix for this thread's chunk
    for (int i = start; i < end; i++) {
        g_off[i] = run;
        run += g_deg[i];
    }
}

__global__ void fill_kernel(const int* __restrict__ edges)
{
    int e = blockIdx.x * blockDim.x + threadIdx.x;
    if (e >= EE) return;
    int dst = edges[EE + e];
    int src = edges[e];
    if ((unsigned)dst >= NN || (unsigned)src >= NN) return;
    g_csr[g_off[dst] + g_rank[e]] = src;
}

// ---------------------------------------------------------------------------
// GEMM: H[r][n] = sum_k act(X[r][k]) * W[n][k] + b[n]
// BM=128, BN=64 (grid.y = 2), BK=32; 256 threads; 8x4 thread tile as
// 4 row-pairs x 4 cols of packed f32x2 FMAs. __launch_bounds__(256,3)
// caps regs at 85 -> 3 CTAs/SM (37.5% occ). Smem 25.6 KB.
// ---------------------------------------------------------------------------
#define LDP  132
#define LDPW 68

template <bool RELU_IN>
__global__ void __launch_bounds__(256, 3) gemm_kernel(
    const float* __restrict__ X, const float* __restrict__ W,
    const float* __restrict__ bias, float* __restrict__ H)
{
    __shared__ float Xs[32][LDP];    // Xs[k][m]
    __shared__ float Ws[32][LDPW];   // Ws[k][n_local], n_local in [0,64)

    const int tid  = threadIdx.x;
    const int row0 = blockIdx.x * 128;
    const int col0 = blockIdx.y * 64;
    const int tr   = tid >> 4;       // 0..15 -> rows tr*8..tr*8+7
    const int tc   = tid & 15;       // 0..15 -> cols tc*4..tc*4+3 (local)

    unsigned long long acc2[4][4];   // [row-pair][col]
    #pragma unroll
    for (int i = 0; i < 4; i++)
        #pragma unroll
        for (int j = 0; j < 4; j++) acc2[i][j] = 0ull;

    for (int kb = 0; kb < DF; kb += 32) {
        // X tile: 128 rows x 32 k = 1024 float4; 4 per thread
        #pragma unroll
        for (int i = 0; i < 4; i++) {
            int idx = tid + i * 256;          // 0..1023
            int r   = idx >> 3;               // 0..127
            int c4  = idx & 7;                // 0..7
            int gr  = row0 + r;
            float4 v = make_float4(0.f, 0.f, 0.f, 0.f);
            if (gr < NN)
                v = *reinterpret_cast<const float4*>(X + (size_t)gr * DF + kb + c4 * 4);
            if (RELU_IN) {
                v.x = fmaxf(v.x, 0.f); v.y = fmaxf(v.y, 0.f);
                v.z = fmaxf(v.z, 0.f); v.w = fmaxf(v.w, 0.f);
            }
            Xs[c4 * 4 + 0][r] = v.x; Xs[c4 * 4 + 1][r] = v.y;
            Xs[c4 * 4 + 2][r] = v.z; Xs[c4 * 4 + 3][r] = v.w;
        }
        // W tile: 64 local cols x 32 k = 512 float4; 2 per thread
        #pragma unroll
        for (int i = 0; i < 2; i++) {
            int idx = tid + i * 256;          // 0..511
            int n   = idx >> 3;               // 0..63
            int c4  = idx & 7;                // 0..7
            float4 v = *reinterpret_cast<const float4*>(
                W + (size_t)(col0 + n) * DF + kb + c4 * 4);
            Ws[c4 * 4 + 0][n] = v.x; Ws[c4 * 4 + 1][n] = v.y;
            Ws[c4 * 4 + 2][n] = v.z; Ws[c4 * 4 + 3][n] = v.w;
        }
        __syncthreads();

        #pragma unroll
        for (int k = 0; k < 32; k++) {
            float4 m0 = *reinterpret_cast<const float4*>(&Xs[k][tr * 8]);
            float4 m1 = *reinterpret_cast<const float4*>(&Xs[k][tr * 8 + 4]);
            float4 n0 = *reinterpret_cast<const float4*>(&Ws[k][tc * 4]);

            unsigned long long ap[4];
            ap[0] = pack2(m0.x, m0.y); ap[1] = pack2(m0.z, m0.w);
            ap[2] = pack2(m1.x, m1.y); ap[3] = pack2(m1.z, m1.w);

            unsigned long long bs[4];
            bs[0] = splat2(n0.x); bs[1] = splat2(n0.y);
            bs[2] = splat2(n0.z); bs[3] = splat2(n0.w);

            #pragma unroll
            for (int i = 0; i < 4; i++)
                #pragma unroll
                for (int j = 0; j < 4; j++)
                    fma2(acc2[i][j], ap[i], bs[j]);
        }
        __syncthreads();
    }

    float bn[4];
    #pragma unroll
    for (int j = 0; j < 4; j++) bn[j] = bias[col0 + tc * 4 + j];

    float accf[8][4];
    #pragma unroll
    for (int i2 = 0; i2 < 4; i2++)
        #pragma unroll
        for (int j = 0; j < 4; j++)
            unpack2(acc2[i2][j], accf[2 * i2][j], accf[2 * i2 + 1][j]);

    #pragma unroll
    for (int i = 0; i < 8; i++) {
        int gr = row0 + tr * 8 + i;
        if (gr < NN) {
            float4 v;
            v.x = accf[i][0] + bn[0];
            v.y = accf[i][1] + bn[1];
            v.z = accf[i][2] + bn[2];
            v.w = accf[i][3] + bn[3];
            *reinterpret_cast<float4*>(H + (size_t)gr * DF + col0 + tc * 4) = v;
        }
    }
}

// ---------------------------------------------------------------------------
// Gather segment-sum: AGG[n] = H[n] + sum_{s in csr[n]} H[s]. One warp/node.
// ---------------------------------------------------------------------------
__device__ __forceinline__ float4 gather_row(int node, int lane,
                                             const float* __restrict__ H)
{
    int start = g_off[node];
    int deg   = g_deg[node];

    float4 acc = *reinterpret_cast<const float4*>(H + (size_t)node * DF + lane * 4);

    for (int j = 0; j < deg; j += 32) {
        int rem  = deg - j;
        int cnt  = rem < 32 ? rem : 32;
        int myi  = (lane < cnt) ? g_csr[start + j + lane] : 0;
        #pragma unroll 4
        for (int k = 0; k < cnt; k++) {
            int s = __shfl_sync(0xffffffffu, myi, k);
            float4 v = *reinterpret_cast<const float4*>(H + (size_t)s * DF + lane * 4);
            acc.x += v.x; acc.y += v.y; acc.z += v.z; acc.w += v.w;
        }
    }
    return acc;
}

__global__ void __launch_bounds__(256) gather_kernel(
    const float* __restrict__ H, float* __restrict__ AGG)
{
    const int w    = (blockIdx.x * blockDim.x + threadIdx.x) >> 5;
    const int lane = threadIdx.x & 31;
    if (w >= NN) return;
    float4 acc = gather_row(w, lane, H);
    *reinterpret_cast<float4*>(AGG + (size_t)w * DF + lane * 4) = acc;
}

// Layer-3 gather fused with head: relu, x_embed, logits, argmax.
__global__ void __launch_bounds__(256) gather_head_kernel(
    const float* __restrict__ H, const float* __restrict__ Wout,
    const float* __restrict__ bout, float* __restrict__ out)
{
    const int w    = (blockIdx.x * blockDim.x + threadIdx.x) >> 5;
    const int lane = threadIdx.x & 31;
    if (w >= NN) return;

    float4 v = gather_row(w, lane, H);
    v.x = fmaxf(v.x, 0.f); v.y = fmaxf(v.y, 0.f);
    v.z = fmaxf(v.z, 0.f); v.w = fmaxf(v.w, 0.f);
    *reinterpret_cast<float4*>(out + (size_t)w * DF + lane * 4) = v;  // x_embed

    float l0, l1, l2;
    {
        float4 w0 = *reinterpret_cast<const float4*>(Wout + 0 * DF + lane * 4);
        float4 w1 = *reinterpret_cast<const float4*>(Wout + 1 * DF + lane * 4);
        float4 w2 = *reinterpret_cast<const float4*>(Wout + 2 * DF + lane * 4);
        l0 = v.x * w0.x + v.y * w0.y + v.z * w0.z + v.w * w0.w;
        l1 = v.x * w1.x + v.y * w1.y + v.z * w1.z + v.w * w1.w;
        l2 = v.x * w2.x + v.y * w2.y + v.z * w2.z + v.w * w2.w;
    }
    #pragma unroll
    for (int off = 16; off > 0; off >>= 1) {
        l0 += __shfl_xor_sync(0xffffffffu, l0, off);
        l1 += __shfl_xor_sync(0xffffffffu, l1, off);
        l2 += __shfl_xor_sync(0xffffffffu, l2, off);
    }
    if (lane == 0) {
        l0 += bout[0]; l1 += bout[1]; l2 += bout[2];
        g_logits[(size_t)w * 3 + 0] = l0;
        g_logits[(size_t)w * 3 + 1] = l1;
        g_logits[(size_t)w * 3 + 2] = l2;
        int am = 0; float best = l0;
        if (l1 > best) { best = l1; am = 1; }
        if (l2 > best) { best = l2; am = 2; }
        out[(size_t)NN * DF + (size_t)MQ * NCLS + w] = (float)am;  // ypred
    }
}

// node_output = logits[node_index]; y_nodepred = ypred[node_index]
__global__ void node_gather_kernel(const int* __restrict__ node_index,
                                   float* __restrict__ out)
{
    int i = blockIdx.x * blockDim.x + threadIdx.x;
    if (i >= MQ) return;
    int n = node_index[i];
    if ((unsigned)n >= NN) n = 0;
    size_t base = (size_t)NN * DF;
    out[base + (size_t)i * 3 + 0] = g_logits[(size_t)n * 3 + 0];
    out[base + (size_t)i * 3 + 1] = g_logits[(size_t)n * 3 + 1];
    out[base + (size_t)i * 3 + 2] = g_logits[(size_t)n * 3 + 2];
    out[base + (size_t)MQ * NCLS + NN + i] = out[base + (size_t)MQ * NCLS + n];
}

// ---------------------------------------------------------------------------
extern "C" void kernel_launch(void* const* d_in, const int* in_sizes, int n_in,
                              void* d_out, int out_size)
{
    const float* x          = (const float*)d_in[0];
    const int*   edges      = (const int*)d_in[1];
    /* d_in[2] node_label: unused (zeros) */
    const int*   node_index = (const int*)d_in[3];
    const float* W1 = (const float*)d_in[4];  const float* b1 = (const float*)d_in[5];
    const float* W2 = (const float*)d_in[6];  const float* b2 = (const float*)d_in[7];
    const float* W3 = (const float*)d_in[8];  const float* b3 = (const float*)d_in[9];
    const float* Wout = (const float*)d_in[10]; const float* bout = (const float*)d_in[11];
    float* out = (float*)d_out;

    float *H, *A;
    cudaGetSymbolAddress((void**)&H, g_H);
    cudaGetSymbolAddress((void**)&A, g_A);
    int* degp;
    cudaGetSymbolAddress((void**)&degp, g_deg);

    const dim3 gemm_grid((NN + 127) / 128, 2);              // 391 x 2
    const int edge_blocks = (EE + 255) / 256;               // 3125
    const int warp_blocks = ((size_t)NN * 32 + 255) / 256;  // 6250

    // Fork: CSR build on side stream, GEMM-1 on main stream (independent).
    cudaEventRecord(g_side.fork, 0);
    cudaStreamWaitEvent(g_side.s, g_side.fork, 0);

    cudaMemsetAsync(degp, 0, NN * sizeof(int), g_side.s);
    hist_kernel<<<edge_blocks, 256, 0, g_side.s>>>(edges);
    scan_kernel<<<1, 1024, 0, g_side.s>>>();
    fill_kernel<<<edge_blocks, 256, 0, g_side.s>>>(edges);
    cudaEventRecord(g_side.join, g_side.s);

    gemm_kernel<false><<<gemm_grid, 256>>>(x, W1, b1, H);   // main stream

    // Join: gather-1 needs both GEMM-1 and the CSR.
    cudaStreamWaitEvent(0, g_side.join, 0);

    gather_kernel<<<warp_blocks, 256>>>(H, A);
    // Layer 2 (relu on read)
    gemm_kernel<true><<<gemm_grid, 256>>>(A, W2, b2, H);
    gather_kernel<<<warp_blocks, 256>>>(H, A);
    // Layer 3 + fused head
    gemm_kernel<true><<<gemm_grid, 256>>>(A, W3, b3, H);
    gather_head_kernel<<<warp_blocks, 256>>>(H, Wout, bout, out);

    node_gather_kernel<<<(MQ + 255) / 256, 256>>>(node_index, out);
}

// round 9
// speedup vs baseline: 1.4110x; 1.0413x over previous
#include <cuda_runtime.h>

#define NN   50000
#define EE   800000
#define DF   128
#define NCLS 3
#define MQ   10000

// Scratch (static device globals — no runtime allocation).
__device__ __align__(16) float g_H[(size_t)NN * DF];
__device__ __align__(16) float g_A[(size_t)NN * DF];
__device__ __align__(16) float g_logits[(size_t)NN * NCLS];
__device__ int g_deg[NN];
__device__ int g_off[NN];
__device__ int g_rank[EE];
__device__ int g_csr[EE];

// Side stream + fork/join events, created at static-init.
struct SideStream {
    cudaStream_t s;
    cudaEvent_t  fork, join;
    SideStream() {
        cudaStreamCreateWithFlags(&s, cudaStreamNonBlocking);
        cudaEventCreateWithFlags(&fork, cudaEventDisableTiming);
        cudaEventCreateWithFlags(&join, cudaEventDisableTiming);
    }
};
static SideStream g_side;

// ---------------------------------------------------------------------------
// Packed f32x2 helpers (Blackwell sm_100a+)
// ---------------------------------------------------------------------------
__device__ __forceinline__ unsigned long long splat2(float v)
{
    unsigned long long r;
    asm("mov.b64 %0, {%1, %1};" : "=l"(r) : "f"(v));
    return r;
}
__device__ __forceinline__ void fma2(unsigned long long& d,
                                     unsigned long long a, unsigned long long b)
{
    asm("fma.rn.f32x2 %0, %1, %2, %0;" : "+l"(d) : "l"(a), "l"(b));
}
__device__ __forceinline__ void unpack2(unsigned long long v, float& lo, float& hi)
{
    asm("mov.b64 {%0, %1}, %2;" : "=f"(lo), "=f"(hi) : "l"(v));
}

// ---------------------------------------------------------------------------
// CSR build: memset(deg) -> histogram(dst) capturing per-edge rank -> scan ->
// fill (NO atomics in fill: position = off[dst] + rank[e])
// ---------------------------------------------------------------------------
__global__ void hist_kernel(const int* __restrict__ edges)
{
    int e = blockIdx.x * blockDim.x + threadIdx.x;
    if (e >= EE) return;
    int dst = edges[EE + e];
    int r = 0;
    if ((unsigned)dst < NN) r = atomicAdd(&g_deg[dst], 1);
    g_rank[e] = r;
}

__global__ void __launch_bounds__(1024) scan_kernel()
{
    __shared__ int sh[1024];
    const int T = 1024;
    const int CH = (NN + T - 1) / T;          // 49
    int t = threadIdx.x;
    int start = t * CH;
    int end   = min(start + CH, NN);

    int s = 0;
    for (int i = start; i < end; i++) s += g_deg[i];
    sh[t] = s;
    __syncthreads();

    for (int off = 1; off < T; off <<= 1) {
        int v = (t >= off) ? sh[t - off] : 0;
        __syncthreads();
        sh[t] += v;
        __syncthreads();
    }
    int run = sh[t] - s;   // exclusive prefix for this thread's chunk
    for (int i = start; i < end; i++) {
        g_off[i] = run;
        run += g_deg[i];
    }
}

__global__ void fill_kernel(const int* __restrict__ edges)
{
    int e = blockIdx.x * blockDim.x + threadIdx.x;
    if (e >= EE) return;
    int dst = edges[EE + e];
    int src = edges[e];
    if ((unsigned)dst >= NN || (unsigned)src >= NN) return;
    g_csr[g_off[dst] + g_rank[e]] = src;
}

// ---------------------------------------------------------------------------
// GEMM: H[r][n] = sum_k act(X[r][k]) * W[n][k] + b[n]
// BM=128, BN=128, BK=32; 256 threads; 8x8 tile as 4 row-pairs x 8 cols of
// packed f32x2 FMAs. A-pairs loaded directly as ulonglong2 from smem (no
// pack MOVs). __launch_bounds__(256,2) -> <=128 regs -> 2 CTA/SM.
// Smem 33.8 KB/CTA.
// ---------------------------------------------------------------------------
#define LDP 132

template <bool RELU_IN>
__global__ void __launch_bounds__(256, 2) gemm_kernel(
    const float* __restrict__ X, const float* __restrict__ W,
    const float* __restrict__ bias, float* __restrict__ H)
{
    __shared__ float Xs[32][LDP];   // Xs[k][m]
    __shared__ float Ws[32][LDP];   // Ws[k][n] = W[n][k_global]

    const int tid  = threadIdx.x;
    const int row0 = blockIdx.x * 128;
    const int tr   = tid >> 4;      // rows tr*8..tr*8+7
    const int tc   = tid & 15;      // cols tc*8..tc*8+7

    unsigned long long acc2[4][8];  // [row-pair][col]
    #pragma unroll
    for (int i = 0; i < 4; i++)
        #pragma unroll
        for (int j = 0; j < 8; j++) acc2[i][j] = 0ull;

    for (int kb = 0; kb < DF; kb += 32) {
        #pragma unroll
        for (int i = 0; i < 4; i++) {
            int idx = tid + i * 256;          // 0..1023
            int r   = idx >> 3;               // 0..127
            int c4  = idx & 7;                // 0..7
            int gr  = row0 + r;
            float4 v = make_float4(0.f, 0.f, 0.f, 0.f);
            if (gr < NN)
                v = *reinterpret_cast<const float4*>(X + (size_t)gr * DF + kb + c4 * 4);
            if (RELU_IN) {
                v.x = fmaxf(v.x, 0.f); v.y = fmaxf(v.y, 0.f);
                v.z = fmaxf(v.z, 0.f); v.w = fmaxf(v.w, 0.f);
            }
            Xs[c4 * 4 + 0][r] = v.x; Xs[c4 * 4 + 1][r] = v.y;
            Xs[c4 * 4 + 2][r] = v.z; Xs[c4 * 4 + 3][r] = v.w;
        }
        #pragma unroll
        for (int i = 0; i < 4; i++) {
            int idx = tid + i * 256;
            int n   = idx >> 3;
            int c4  = idx & 7;
            float4 v = *reinterpret_cast<const float4*>(W + (size_t)n * DF + kb + c4 * 4);
            Ws[c4 * 4 + 0][n] = v.x; Ws[c4 * 4 + 1][n] = v.y;
            Ws[c4 * 4 + 2][n] = v.z; Ws[c4 * 4 + 3][n] = v.w;
        }
        __syncthreads();

        #pragma unroll
        for (int k = 0; k < 32; k++) {
            // A row-pairs: adjacent floats in smem ARE the packed f32x2 pair.
            ulonglong2 a01 = *reinterpret_cast<const ulonglong2*>(&Xs[k][tr * 8]);
            ulonglong2 a23 = *reinterpret_cast<const ulonglong2*>(&Xs[k][tr * 8 + 4]);
            float4 n0 = *reinterpret_cast<const float4*>(&Ws[k][tc * 8]);
            float4 n1 = *reinterpret_cast<const float4*>(&Ws[k][tc * 8 + 4]);

            unsigned long long ap[4] = {a01.x, a01.y, a23.x, a23.y};
            unsigned long long bs[8];
            bs[0] = splat2(n0.x); bs[1] = splat2(n0.y);
            bs[2] = splat2(n0.z); bs[3] = splat2(n0.w);
            bs[4] = splat2(n1.x); bs[5] = splat2(n1.y);
            bs[6] = splat2(n1.z); bs[7] = splat2(n1.w);

            #pragma unroll
            for (int i = 0; i < 4; i++)
                #pragma unroll
                for (int j = 0; j < 8; j++)
                    fma2(acc2[i][j], ap[i], bs[j]);
        }
        __syncthreads();
    }

    float bn[8];
    #pragma unroll
    for (int j = 0; j < 8; j++) bn[j] = bias[tc * 8 + j];

    float accf[8][8];
    #pragma unroll
    for (int i2 = 0; i2 < 4; i2++)
        #pragma unroll
        for (int j = 0; j < 8; j++)
            unpack2(acc2[i2][j], accf[2 * i2][j], accf[2 * i2 + 1][j]);

    #pragma unroll
    for (int i = 0; i < 8; i++) {
        int gr = row0 + tr * 8 + i;
        if (gr < NN) {
            #pragma unroll
            for (int j = 0; j < 8; j += 4) {
                float4 v;
                v.x = accf[i][j + 0] + bn[j + 0];
                v.y = accf[i][j + 1] + bn[j + 1];
                v.z = accf[i][j + 2] + bn[j + 2];
                v.w = accf[i][j + 3] + bn[j + 3];
                *reinterpret_cast<float4*>(H + (size_t)gr * DF + tc * 8 + j) = v;
            }
        }
    }
}

// ---------------------------------------------------------------------------
// Gather segment-sum: AGG[n] = H[n] + sum_{s in csr[n]} H[s]. One warp/node.
// ---------------------------------------------------------------------------
__device__ __forceinline__ float4 gather_row(int node, int lane,
                                             const float* __restrict__ H)
{
    int start = g_off[node];
    int deg   = g_deg[node];

    float4 acc = *reinterpret_cast<const float4*>(H + (size_t)node * DF + lane * 4);

    for (int j = 0; j < deg; j += 32) {
        int rem  = deg - j;
        int cnt  = rem < 32 ? rem : 32;
        int myi  = (lane < cnt) ? g_csr[start + j + lane] : 0;
        #pragma unroll 4
        for (int k = 0; k < cnt; k++) {
            int s = __shfl_sync(0xffffffffu, myi, k);
            float4 v = *reinterpret_cast<const float4*>(H + (size_t)s * DF + lane * 4);
            acc.x += v.x; acc.y += v.y; acc.z += v.z; acc.w += v.w;
        }
    }
    return acc;
}

__global__ void __launch_bounds__(256) gather_kernel(
    const float* __restrict__ H, float* __restrict__ AGG)
{
    const int w    = (blockIdx.x * blockDim.x + threadIdx.x) >> 5;
    const int lane = threadIdx.x & 31;
    if (w >= NN) return;
    float4 acc = gather_row(w, lane, H);
    *reinterpret_cast<float4*>(AGG + (size_t)w * DF + lane * 4) = acc;
}

// Layer-3 gather fused with head: relu, x_embed, logits, argmax.
__global__ void __launch_bounds__(256) gather_head_kernel(
    const float* __restrict__ H, const float* __restrict__ Wout,
    const float* __restrict__ bout, float* __restrict__ out)
{
    const int w    = (blockIdx.x * blockDim.x + threadIdx.x) >> 5;
    const int lane = threadIdx.x & 31;
    if (w >= NN) return;

    float4 v = gather_row(w, lane, H);
    v.x = fmaxf(v.x, 0.f); v.y = fmaxf(v.y, 0.f);
    v.z = fmaxf(v.z, 0.f); v.w = fmaxf(v.w, 0.f);
    *reinterpret_cast<float4*>(out + (size_t)w * DF + lane * 4) = v;  // x_embed

    float l0, l1, l2;
    {
        float4 w0 = *reinterpret_cast<const float4*>(Wout + 0 * DF + lane * 4);
        float4 w1 = *reinterpret_cast<const float4*>(Wout + 1 * DF + lane * 4);
        float4 w2 = *reinterpret_cast<const float4*>(Wout + 2 * DF + lane * 4);
        l0 = v.x * w0.x + v.y * w0.y + v.z * w0.z + v.w * w0.w;
        l1 = v.x * w1.x + v.y * w1.y + v.z * w1.z + v.w * w1.w;
        l2 = v.x * w2.x + v.y * w2.y + v.z * w2.z + v.w * w2.w;
    }
    #pragma unroll
    for (int off = 16; off > 0; off >>= 1) {
        l0 += __shfl_xor_sync(0xffffffffu, l0, off);
        l1 += __shfl_xor_sync(0xffffffffu, l1, off);
        l2 += __shfl_xor_sync(0xffffffffu, l2, off);
    }
    if (lane == 0) {
        l0 += bout[0]; l1 += bout[1]; l2 += bout[2];
        g_logits[(size_t)w * 3 + 0] = l0;
        g_logits[(size_t)w * 3 + 1] = l1;
        g_logits[(size_t)w * 3 + 2] = l2;
        int am = 0; float best = l0;
        if (l1 > best) { best = l1; am = 1; }
        if (l2 > best) { best = l2; am = 2; }
        out[(size_t)NN * DF + (size_t)MQ * NCLS + w] = (float)am;  // ypred
    }
}

// node_output = logits[node_index]; y_nodepred = ypred[node_index]
__global__ void node_gather_kernel(const int* __restrict__ node_index,
                                   float* __restrict__ out)
{
    int i = blockIdx.x * blockDim.x + threadIdx.x;
    if (i >= MQ) return;
    int n = node_index[i];
    if ((unsigned)n >= NN) n = 0;
    size_t base = (size_t)NN * DF;
    out[base + (size_t)i * 3 + 0] = g_logits[(size_t)n * 3 + 0];
    out[base + (size_t)i * 3 + 1] = g_logits[(size_t)n * 3 + 1];
    out[base + (size_t)i * 3 + 2] = g_logits[(size_t)n * 3 + 2];
    out[base + (size_t)MQ * NCLS + NN + i] = out[base + (size_t)MQ * NCLS + n];
}

// ---------------------------------------------------------------------------
extern "C" void kernel_launch(void* const* d_in, const int* in_sizes, int n_in,
                              void* d_out, int out_size)
{
    const float* x          = (const float*)d_in[0];
    const int*   edges      = (const int*)d_in[1];
    /* d_in[2] node_label: unused (zeros) */
    const int*   node_index = (const int*)d_in[3];
    const float* W1 = (const float*)d_in[4];  const float* b1 = (const float*)d_in[5];
    const float* W2 = (const float*)d_in[6];  const float* b2 = (const float*)d_in[7];
    const float* W3 = (const float*)d_in[8];  const float* b3 = (const float*)d_in[9];
    const float* Wout = (const float*)d_in[10]; const float* bout = (const float*)d_in[11];
    float* out = (float*)d_out;

    float *H, *A;
    cudaGetSymbolAddress((void**)&H, g_H);
    cudaGetSymbolAddress((void**)&A, g_A);
    int* degp;
    cudaGetSymbolAddress((void**)&degp, g_deg);

    const int gemm_blocks = (NN + 127) / 128;               // 391
    const int edge_blocks = (EE + 255) / 256;               // 3125
    const int warp_blocks = ((size_t)NN * 32 + 255) / 256;  // 6250

    // Fork: CSR build on side stream, GEMM-1 on main stream (independent).
    cudaEventRecord(g_side.fork, 0);
    cudaStreamWaitEvent(g_side.s, g_side.fork, 0);

    cudaMemsetAsync(degp, 0, NN * sizeof(int), g_side.s);
    hist_kernel<<<edge_blocks, 256, 0, g_side.s>>>(edges);
    scan_kernel<<<1, 1024, 0, g_side.s>>>();
    fill_kernel<<<edge_blocks, 256, 0, g_side.s>>>(edges);
    cudaEventRecord(g_side.join, g_side.s);

    gemm_kernel<false><<<gemm_blocks, 256>>>(x, W1, b1, H);   // main stream

    // Join: gather-1 needs both GEMM-1 and the CSR.
    cudaStreamWaitEvent(0, g_side.join, 0);

    gather_kernel<<<warp_blocks, 256>>>(H, A);
    // Layer 2 (relu on read)
    gemm_kernel<true><<<gemm_blocks, 256>>>(A, W2, b2, H);
    gather_kernel<<<warp_blocks, 256>>>(H, A);
    // Layer 3 + fused head
    gemm_kernel<true><<<gemm_blocks, 256>>>(A, W3, b3, H);
    gather_head_kernel<<<warp_blocks, 256>>>(H, Wout, bout, out);

    node_gather_kernel<<<(MQ + 255) / 256, 256>>>(node_index, out);
}

// round 10
// speedup vs baseline: 1.4892x; 1.0554x over previous
#include <cuda_runtime.h>

#define NN   50000
#define EE   800000
#define DF   128
#define NCLS 3
#define MQ   10000

// Scratch (static device globals — no runtime allocation).
__device__ __align__(16) float g_H[(size_t)NN * DF];
__device__ __align__(16) float g_A[(size_t)NN * DF];
__device__ __align__(16) float g_logits[(size_t)NN * NCLS];
__device__ int g_deg[NN];
__device__ int g_off[NN];
__device__ int g_rank[EE];
__device__ int g_csr[EE];

// Side stream + fork/join events, created at static-init.
struct SideStream {
    cudaStream_t s;
    cudaEvent_t  fork, join;
    SideStream() {
        cudaStreamCreateWithFlags(&s, cudaStreamNonBlocking);
        cudaEventCreateWithFlags(&fork, cudaEventDisableTiming);
        cudaEventCreateWithFlags(&join, cudaEventDisableTiming);
    }
};
static SideStream g_side;

// ---------------------------------------------------------------------------
// Packed f32x2 helpers (Blackwell sm_100a+)
// ---------------------------------------------------------------------------
__device__ __forceinline__ unsigned long long splat2(float v)
{
    unsigned long long r;
    asm("mov.b64 %0, {%1, %1};" : "=l"(r) : "f"(v));
    return r;
}
__device__ __forceinline__ void fma2(unsigned long long& d,
                                     unsigned long long a, unsigned long long b)
{
    asm("fma.rn.f32x2 %0, %1, %2, %0;" : "+l"(d) : "l"(a), "l"(b));
}
__device__ __forceinline__ void unpack2(unsigned long long v, float& lo, float& hi)
{
    asm("mov.b64 {%0, %1}, %2;" : "=f"(lo), "=f"(hi) : "l"(v));
}

// ---------------------------------------------------------------------------
// CSR build: memset(deg) -> histogram(dst) capturing per-edge rank -> scan ->
// fill (NO atomics in fill: position = off[dst] + rank[e])
// ---------------------------------------------------------------------------
__global__ void hist_kernel(const int* __restrict__ edges)
{
    int e = blockIdx.x * blockDim.x + threadIdx.x;
    if (e >= EE) return;
    int dst = edges[EE + e];
    int r = 0;
    if ((unsigned)dst < NN) r = atomicAdd(&g_deg[dst], 1);
    g_rank[e] = r;
}

__global__ void __launch_bounds__(1024) scan_kernel()
{
    __shared__ int sh[1024];
    const int T = 1024;
    const int CH = (NN + T - 1) / T;          // 49
    int t = threadIdx.x;
    int start = t * CH;
    int end   = min(start + CH, NN);

    int s = 0;
    for (int i = start; i < end; i++) s += g_deg[i];
    sh[t] = s;
    __syncthreads();

    for (int off = 1; off < T; off <<= 1) {
        int v = (t >= off) ? sh[t - off] : 0;
        __syncthreads();
        sh[t] += v;
        __syncthreads();
    }
    int run = sh[t] - s;   // exclusive prefix for this thread's chunk
    for (int i = start; i < end; i++) {
        g_off[i] = run;
        run += g_deg[i];
    }
}

__global__ void fill_kernel(const int* __restrict__ edges)
{
    int e = blockIdx.x * blockDim.x + threadIdx.x;
    if (e >= EE) return;
    int dst = edges[EE + e];
    int src = edges[e];
    if ((unsigned)dst >= NN || (unsigned)src >= NN) return;
    g_csr[g_off[dst] + g_rank[e]] = src;
}

// ---------------------------------------------------------------------------
// GEMM: H[r][n] = sum_k act(X[r][k]) * W[n][k] + b[n]
// BM=128, BN=128, BK=32; 256 threads; 8x8 tile as 4 row-pairs x 8 cols of
// packed f32x2 FMAs. B tile split into two half-tiles (WsA: cols c%8<4,
// WsB: cols c%8>=4) so each B-fragment load is 16 contiguous bytes per lane
// -> conflict-free LDS. __launch_bounds__(256,2).
// ---------------------------------------------------------------------------
#define LDP  132   // Xs row stride (floats)
#define LDPW 68    // WsA/WsB row stride (floats), 64 + 4 pad

template <bool RELU_IN>
__global__ void __launch_bounds__(256, 2) gemm_kernel(
    const float* __restrict__ X, const float* __restrict__ W,
    const float* __restrict__ bias, float* __restrict__ H)
{
    __shared__ float Xs [32][LDP];    // Xs[k][m]
    __shared__ float WsA[32][LDPW];   // WsA[k][grp*4+c] = W[grp*8+c][k],   c<4
    __shared__ float WsB[32][LDPW];   // WsB[k][grp*4+c] = W[grp*8+4+c][k]

    const int tid  = threadIdx.x;
    const int row0 = blockIdx.x * 128;
    const int tr   = tid >> 4;      // rows tr*8..tr*8+7
    const int tc   = tid & 15;      // col group: cols tc*8..tc*8+7

    unsigned long long acc2[4][8];  // [row-pair][col]
    #pragma unroll
    for (int i = 0; i < 4; i++)
        #pragma unroll
        for (int j = 0; j < 8; j++) acc2[i][j] = 0ull;

    for (int kb = 0; kb < DF; kb += 32) {
        #pragma unroll
        for (int i = 0; i < 4; i++) {
            int idx = tid + i * 256;          // 0..1023
            int r   = idx >> 3;               // 0..127
            int c4  = idx & 7;                // 0..7
            int gr  = row0 + r;
            float4 v = make_float4(0.f, 0.f, 0.f, 0.f);
            if (gr < NN)
                v = *reinterpret_cast<const float4*>(X + (size_t)gr * DF + kb + c4 * 4);
            if (RELU_IN) {
                v.x = fmaxf(v.x, 0.f); v.y = fmaxf(v.y, 0.f);
                v.z = fmaxf(v.z, 0.f); v.w = fmaxf(v.w, 0.f);
            }
            Xs[c4 * 4 + 0][r] = v.x; Xs[c4 * 4 + 1][r] = v.y;
            Xs[c4 * 4 + 2][r] = v.z; Xs[c4 * 4 + 3][r] = v.w;
        }
        #pragma unroll
        for (int i = 0; i < 4; i++) {
            int idx = tid + i * 256;
            int n   = idx >> 3;               // 0..127 (output col)
            int c4  = idx & 7;                // k sub-group
            float4 v = *reinterpret_cast<const float4*>(W + (size_t)n * DF + kb + c4 * 4);
            int grp = n >> 3;
            int c   = n & 7;
            float* dstcol = (c < 4) ? &WsA[0][grp * 4 + c] : &WsB[0][grp * 4 + (c - 4)];
            dstcol[(c4 * 4 + 0) * LDPW] = v.x;
            dstcol[(c4 * 4 + 1) * LDPW] = v.y;
            dstcol[(c4 * 4 + 2) * LDPW] = v.z;
            dstcol[(c4 * 4 + 3) * LDPW] = v.w;
        }
        __syncthreads();

        #pragma unroll
        for (int k = 0; k < 32; k++) {
            // A row-pairs: adjacent floats in smem ARE the packed f32x2 pair.
            ulonglong2 a01 = *reinterpret_cast<const ulonglong2*>(&Xs[k][tr * 8]);
            ulonglong2 a23 = *reinterpret_cast<const ulonglong2*>(&Xs[k][tr * 8 + 4]);
            // B fragments: contiguous 16B per lane -> conflict-free.
            float4 n0 = *reinterpret_cast<const float4*>(&WsA[k][tc * 4]);
            float4 n1 = *reinterpret_cast<const float4*>(&WsB[k][tc * 4]);

            unsigned long long ap[4] = {a01.x, a01.y, a23.x, a23.y};
            unsigned long long bs[8];
            bs[0] = splat2(n0.x); bs[1] = splat2(n0.y);
            bs[2] = splat2(n0.z); bs[3] = splat2(n0.w);
            bs[4] = splat2(n1.x); bs[5] = splat2(n1.y);
            bs[6] = splat2(n1.z); bs[7] = splat2(n1.w);

            #pragma unroll
            for (int i = 0; i < 4; i++) {
                #pragma unroll
                for (int j = 0; j < 4; j++) fma2(acc2[i][j], ap[i], bs[j]);
                #pragma unroll
                for (int j = 4; j < 8; j++) fma2(acc2[i][j], ap[i], bs[j]);
            }
        }
        __syncthreads();
    }

    // Output cols: j=0..3 -> tc*8+j (from WsA), j=4..7 -> tc*8+j (WsB order
    // matches: bs[4+c] is col tc*8+4+c). Same mapping as before.
    float bn[8];
    #pragma unroll
    for (int j = 0; j < 8; j++) bn[j] = bias[tc * 8 + j];

    float accf[8][8];
    #pragma unroll
    for (int i2 = 0; i2 < 4; i2++)
        #pragma unroll
        for (int j = 0; j < 8; j++)
            unpack2(acc2[i2][j], accf[2 * i2][j], accf[2 * i2 + 1][j]);

    #pragma unroll
    for (int i = 0; i < 8; i++) {
        int gr = row0 + tr * 8 + i;
        if (gr < NN) {
            #pragma unroll
            for (int j = 0; j < 8; j += 4) {
                float4 v;
                v.x = accf[i][j + 0] + bn[j + 0];
                v.y = accf[i][j + 1] + bn[j + 1];
                v.z = accf[i][j + 2] + bn[j + 2];
                v.w = accf[i][j + 3] + bn[j + 3];
                *reinterpret_cast<float4*>(H + (size_t)gr * DF + tc * 8 + j) = v;
            }
        }
    }
}

// ---------------------------------------------------------------------------
// Gather segment-sum: AGG[n] = H[n] + sum_{s in csr[n]} H[s]. One warp/node.
// ---------------------------------------------------------------------------
__device__ __forceinline__ float4 gather_row(int node, int lane,
                                             const float* __restrict__ H)
{
    int start = g_off[node];
    int deg   = g_deg[node];

    float4 acc = *reinterpret_cast<const float4*>(H + (size_t)node * DF + lane * 4);

    for (int j = 0; j < deg; j += 32) {
        int rem  = deg - j;
        int cnt  = rem < 32 ? rem : 32;
        int myi  = (lane < cnt) ? g_csr[start + j + lane] : 0;
        #pragma unroll 4
        for (int k = 0; k < cnt; k++) {
            int s = __shfl_sync(0xffffffffu, myi, k);
            float4 v = *reinterpret_cast<const float4*>(H + (size_t)s * DF + lane * 4);
            acc.x += v.x; acc.y += v.y; acc.z += v.z; acc.w += v.w;
        }
    }
    return acc;
}

__global__ void __launch_bounds__(256) gather_kernel(
    const float* __restrict__ H, float* __restrict__ AGG)
{
    const int w    = (blockIdx.x * blockDim.x + threadIdx.x) >> 5;
    const int lane = threadIdx.x & 31;
    if (w >= NN) return;
    float4 acc = gather_row(w, lane, H);
    *reinterpret_cast<float4*>(AGG + (size_t)w * DF + lane * 4) = acc;
}

// Layer-3 gather fused with head: relu, x_embed, logits, argmax.
__global__ void __launch_bounds__(256) gather_head_kernel(
    const float* __restrict__ H, const float* __restrict__ Wout,
    const float* __restrict__ bout, float* __restrict__ out)
{
    const int w    = (blockIdx.x * blockDim.x + threadIdx.x) >> 5;
    const int lane = threadIdx.x & 31;
    if (w >= NN) return;

    float4 v = gather_row(w, lane, H);
    v.x = fmaxf(v.x, 0.f); v.y = fmaxf(v.y, 0.f);
    v.z = fmaxf(v.z, 0.f); v.w = fmaxf(v.w, 0.f);
    *reinterpret_cast<float4*>(out + (size_t)w * DF + lane * 4) = v;  // x_embed

    float l0, l1, l2;
    {
        float4 w0 = *reinterpret_cast<const float4*>(Wout + 0 * DF + lane * 4);
        float4 w1 = *reinterpret_cast<const float4*>(Wout + 1 * DF + lane * 4);
        float4 w2 = *reinterpret_cast<const float4*>(Wout + 2 * DF + lane * 4);
        l0 = v.x * w0.x + v.y * w0.y + v.z * w0.z + v.w * w0.w;
        l1 = v.x * w1.x + v.y * w1.y + v.z * w1.z + v.w * w1.w;
        l2 = v.x * w2.x + v.y * w2.y + v.z * w2.z + v.w * w2.w;
    }
    #pragma unroll
    for (int off = 16; off > 0; off >>= 1) {
        l0 += __shfl_xor_sync(0xffffffffu, l0, off);
        l1 += __shfl_xor_sync(0xffffffffu, l1, off);
        l2 += __shfl_xor_sync(0xffffffffu, l2, off);
    }
    if (lane == 0) {
        l0 += bout[0]; l1 += bout[1]; l2 += bout[2];
        g_logits[(size_t)w * 3 + 0] = l0;
        g_logits[(size_t)w * 3 + 1] = l1;
        g_logits[(size_t)w * 3 + 2] = l2;
        int am = 0; float best = l0;
        if (l1 > best) { best = l1; am = 1; }
        if (l2 > best) { best = l2; am = 2; }
        out[(size_t)NN * DF + (size_t)MQ * NCLS + w] = (float)am;  // ypred
    }
}

// node_output = logits[node_index]; y_nodepred = ypred[node_index]
__global__ void node_gather_kernel(const int* __restrict__ node_index,
                                   float* __restrict__ out)
{
    int i = blockIdx.x * blockDim.x + threadIdx.x;
    if (i >= MQ) return;
    int n = node_index[i];
    if ((unsigned)n >= NN) n = 0;
    size_t base = (size_t)NN * DF;
    out[base + (size_t)i * 3 + 0] = g_logits[(size_t)n * 3 + 0];
    out[base + (size_t)i * 3 + 1] = g_logits[(size_t)n * 3 + 1];
    out[base + (size_t)i * 3 + 2] = g_logits[(size_t)n * 3 + 2];
    out[base + (size_t)MQ * NCLS + NN + i] = out[base + (size_t)MQ * NCLS + n];
}

// ---------------------------------------------------------------------------
extern "C" void kernel_launch(void* const* d_in, const int* in_sizes, int n_in,
                              void* d_out, int out_size)
{
    const float* x          = (const float*)d_in[0];
    const int*   edges      = (const int*)d_in[1];
    /* d_in[2] node_label: unused (zeros) */
    const int*   node_index = (const int*)d_in[3];
    const float* W1 = (const float*)d_in[4];  const float* b1 = (const float*)d_in[5];
    const float* W2 = (const float*)d_in[6];  const float* b2 = (const float*)d_in[7];
    const float* W3 = (const float*)d_in[8];  const float* b3 = (const float*)d_in[9];
    const float* Wout = (const float*)d_in[10]; const float* bout = (const float*)d_in[11];
    float* out = (float*)d_out;

    float *H, *A;
    cudaGetSymbolAddress((void**)&H, g_H);
    cudaGetSymbolAddress((void**)&A, g_A);
    int* degp;
    cudaGetSymbolAddress((void**)&degp, g_deg);

    const int gemm_blocks = (NN + 127) / 128;               // 391
    const int edge_blocks = (EE + 255) / 256;               // 3125
    const int warp_blocks = ((size_t)NN * 32 + 255) / 256;  // 6250

    // Fork: CSR build on side stream, GEMM-1 on main stream (independent).
    cudaEventRecord(g_side.fork, 0);
    cudaStreamWaitEvent(g_side.s, g_side.fork, 0);

    cudaMemsetAsync(degp, 0, NN * sizeof(int), g_side.s);
    hist_kernel<<<edge_blocks, 256, 0, g_side.s>>>(edges);
    scan_kernel<<<1, 1024, 0, g_side.s>>>();
    fill_kernel<<<edge_blocks, 256, 0, g_side.s>>>(edges);
    cudaEventRecord(g_side.join, g_side.s);

    gemm_kernel<false><<<gemm_blocks, 256>>>(x, W1, b1, H);   // main stream

    // Join: gather-1 needs both GEMM-1 and the CSR.
    cudaStreamWaitEvent(0, g_side.join, 0);

    gather_kernel<<<warp_blocks, 256>>>(H, A);
    // Layer 2 (relu on read)
    gemm_kernel<true><<<gemm_blocks, 256>>>(A, W2, b2, H);
    gather_kernel<<<warp_blocks, 256>>>(H, A);
    // Layer 3 + fused head
    gemm_kernel<true><<<gemm_blocks, 256>>>(A, W3, b3, H);
    gather_head_kernel<<<warp_blocks, 256>>>(H, Wout, bout, out);

    node_gather_kernel<<<(MQ + 255) / 256, 256>>>(node_index, out);
}